// round 7
// baseline (speedup 1.0000x reference)
#include <cuda_runtime.h>

#define B_  4
#define C_  64
#define K_  32
#define N_  131072           // D*H*W
#define XS  260              // X tile row stride (words)
#define LS  260              // L/A tile row stride (words)
#define CWS 36               // transposed codeword stride
#define E_ELEMS (B_*K_*C_)   // 8192

__device__ float g_asum[B_*K_];

typedef unsigned long long u64;

__device__ __forceinline__ u64 ffma2(u64 a, u64 b, u64 c) {
    u64 d; asm("fma.rn.f32x2 %0, %1, %2, %3;" : "=l"(d) : "l"(a), "l"(b), "l"(c));
    return d;
}
__device__ __forceinline__ u64 fadd2(u64 a, u64 b) {
    u64 d; asm("add.rn.f32x2 %0, %1, %2;" : "=l"(d) : "l"(a), "l"(b));
    return d;
}
__device__ __forceinline__ u64 pack2(float lo, float hi) {
    u64 d; asm("mov.b64 %0, {%1, %2};" : "=l"(d) : "f"(lo), "f"(hi));
    return d;
}
__device__ __forceinline__ float2 unpack2(u64 v) {
    float2 r; asm("mov.b64 {%0, %1}, %2;" : "=f"(r.x), "=f"(r.y) : "l"(v));
    return r;
}

// ---------------------------------------------------------------------------
__global__ void enc_init(float* __restrict__ out) {
    int i = blockIdx.x * 256 + threadIdx.x;
    if (i < E_ELEMS) out[i] = 0.0f;
    if (i < B_*K_)   g_asum[i] = 0.0f;
}

// ---------------------------------------------------------------------------
__global__ __launch_bounds__(256, 2) void enc_main(
    const float* __restrict__ X,    // (B, C, N)
    const float* __restrict__ cwg,  // (K, C)
    const float* __restrict__ sclg, // (K,)
    float* __restrict__ out)        // [E | coefA]
{
    extern __shared__ float sm[];
    float* Xs  = sm;                  // 64*260  X tile, swizzled
    float* Lb  = Xs + 64*XS;          // 32*260  logits -> A, swizzled
    float* cwt = Lb + 32*LS;          // 64*36   codewords^T pre-scaled by -2*scl
    float* x2s = cwt + 64*CWS;        // 256
    float* cc  = x2s + 256;           // 64  (float2 per k: scl, scl*|c|^2)

    const int tid = threadIdx.x;
    const int b   = blockIdx.x >> 9;
    const int n0  = (blockIdx.x & 511) << 8;

    // ---- stage X tile, swizzled: word(c,n) = c*XS + ((n4 ^ ((c>>2)&7))<<2 | n&3)
    const float* Xb = X + (size_t)b * C_ * N_ + n0;
    #pragma unroll
    for (int i = 0; i < 16; ++i) {
        int f = i * 256 + tid;
        int c = f >> 6, q = f & 63;          // q = n4
        float4 v = *(const float4*)(Xb + (size_t)c * N_ + q * 4);
        int sc = (c >> 2) & 7;
        *(float4*)(Xs + c * XS + ((q ^ sc) << 2)) = v;
    }
    // ---- stage codewords transposed + pre-scaled by -2*scl[k]
    #pragma unroll
    for (int i = 0; i < 8; ++i) {
        int f = i * 256 + tid;               // f = k*64 + c
        int k = f >> 6, c = f & 63;
        cwt[c * CWS + k] = -2.0f * __ldg(&sclg[k]) * cwg[f];
    }
    // ---- per-k softmax constants straight from global (tiny, L2-hot)
    if (tid < K_) {
        float s = 0.f;
        #pragma unroll
        for (int c = 0; c < C_; ++c) { float w = cwg[tid*C_ + c]; s = fmaf(w, w, s); }
        float sc = sclg[tid];
        *(float2*)(cc + tid * 2) = make_float2(sc, sc * s);
    }
    __syncthreads();

    // ---- Phase 1: scaled-dot GEMM, 4k x 8n per thread, n-paired f32x2 ----
    const int k0  = (tid & 7) * 4;
    const int nt  = (tid >> 3) * 8;
    const int n4a = nt >> 2;                 // even
    u64 acc[4][4];                           // [npair][k] ; holds -2*scl*dot
    u64 x2a[4];
    #pragma unroll
    for (int i = 0; i < 4; ++i) {
        x2a[i] = 0ull;
        #pragma unroll
        for (int j = 0; j < 4; ++j) acc[i][j] = 0ull;
    }

    #pragma unroll 8
    for (int c = 0; c < 64; ++c) {
        int sc = (c >> 2) & 7;
        const float* xr = Xs + c * XS;
        ulonglong2 xa = *(const ulonglong2*)(xr + (( n4a      ^ sc) << 2));
        ulonglong2 xb = *(const ulonglong2*)(xr + (((n4a + 1) ^ sc) << 2));
        float4 w = *(const float4*)(cwt + c * CWS + k0);
        u64 w0 = pack2(w.x, w.x), w1 = pack2(w.y, w.y);
        u64 w2 = pack2(w.z, w.z), w3 = pack2(w.w, w.w);
        acc[0][0] = ffma2(xa.x, w0, acc[0][0]);
        acc[0][1] = ffma2(xa.x, w1, acc[0][1]);
        acc[0][2] = ffma2(xa.x, w2, acc[0][2]);
        acc[0][3] = ffma2(xa.x, w3, acc[0][3]);
        acc[1][0] = ffma2(xa.y, w0, acc[1][0]);
        acc[1][1] = ffma2(xa.y, w1, acc[1][1]);
        acc[1][2] = ffma2(xa.y, w2, acc[1][2]);
        acc[1][3] = ffma2(xa.y, w3, acc[1][3]);
        acc[2][0] = ffma2(xb.x, w0, acc[2][0]);
        acc[2][1] = ffma2(xb.x, w1, acc[2][1]);
        acc[2][2] = ffma2(xb.x, w2, acc[2][2]);
        acc[2][3] = ffma2(xb.x, w3, acc[2][3]);
        acc[3][0] = ffma2(xb.y, w0, acc[3][0]);
        acc[3][1] = ffma2(xb.y, w1, acc[3][1]);
        acc[3][2] = ffma2(xb.y, w2, acc[3][2]);
        acc[3][3] = ffma2(xb.y, w3, acc[3][3]);
        x2a[0] = ffma2(xa.x, xa.x, x2a[0]);
        x2a[1] = ffma2(xa.y, xa.y, x2a[1]);
        x2a[2] = ffma2(xb.x, xb.x, x2a[2]);
        x2a[3] = ffma2(xb.y, xb.y, x2a[3]);
    }
    // store to Lb (swizzled): row k0+j, word nt+2i
    {
        const int sk = tid & 7;              // (k0+j)>>2 for j<4
        #pragma unroll
        for (int j = 0; j < 4; ++j) {
            float* row = Lb + (k0 + j) * LS;
            #pragma unroll
            for (int i = 0; i < 4; ++i) {
                int w4 = (n4a + (i >> 1)) ^ sk;
                *(u64*)(row + (w4 << 2) + 2 * (i & 1)) = acc[i][j];
            }
        }
        if ((tid & 7) == 0) {
            #pragma unroll
            for (int i = 0; i < 4; ++i) *(u64*)(x2s + nt + 2*i) = x2a[i];
        }
    }
    __syncthreads();

    // ---- Softmax per n = tid; coefA out; A back into Lb (same words) ----
    {
        float x2 = x2s[tid];
        const int n4t = tid >> 2, nlo = tid & 3;
        float lg[K_];
        float mx = -1e30f;
        #pragma unroll
        for (int k = 0; k < K_; ++k) {
            float2 t = *(const float2*)(cc + 2 * k);
            float d = Lb[k * LS + (((n4t) ^ ((k >> 2) & 7)) << 2) + nlo];
            float l = d + fmaf(t.x, x2, t.y);     // -2*scl*dot + scl*x2 + scl*c2
            lg[k] = l;
            mx = fmaxf(mx, l);
        }
        float s = 0.f;
        #pragma unroll
        for (int k = 0; k < K_; ++k) { float e = __expf(lg[k] - mx); lg[k] = e; s += e; }
        float inv = __fdividef(1.f, s);
        float* coefA = out + E_ELEMS + (size_t)b * K_ * N_ + n0 + tid;
        #pragma unroll
        for (int k = 0; k < K_; ++k) {
            float a = lg[k] * inv;
            coefA[(size_t)k * N_] = a;
            Lb[k * LS + (((n4t) ^ ((k >> 2) & 7)) << 2) + nlo] = a;
        }
    }
    __syncthreads();

    // ---- Phase 2: A^T X, 8k x 4c per thread over 64 n ----
    {
        const int ns  = tid >> 6;            // n-split 0..3 (64 n each)
        const int pos = tid & 63;
        const int kg  = pos >> 4;            // 0..3 -> k rows 8kg..8kg+7
        const int cg  = pos & 15;            // 0..15 -> c cols 4cg..4cg+3
        const int k0b = kg * 8, c0 = cg * 4;
        const int nb0 = ns * 16;             // n4 base
        const int scx = cg & 7;              // swizzle key for c = cg*4 + cj  (FIX)

        u64 e[8][4];
        u64 sa[8];
        #pragma unroll
        for (int j = 0; j < 8; ++j) {
            sa[j] = 0ull;
            #pragma unroll
            for (int cj = 0; cj < 4; ++cj) e[j][cj] = 0ull;
        }

        #pragma unroll 2
        for (int n4 = 0; n4 < 16; ++n4) {
            const int nb = nb0 + n4;
            const int wx = (nb ^ scx) << 2;
            ulonglong2 xv0 = *(const ulonglong2*)(Xs + (c0+0)*XS + wx);
            ulonglong2 xv1 = *(const ulonglong2*)(Xs + (c0+1)*XS + wx);
            ulonglong2 xv2 = *(const ulonglong2*)(Xs + (c0+2)*XS + wx);
            ulonglong2 xv3 = *(const ulonglong2*)(Xs + (c0+3)*XS + wx);
            #pragma unroll
            for (int j = 0; j < 8; ++j) {
                const int k = k0b + j;
                ulonglong2 av = *(const ulonglong2*)(Lb + k*LS + ((nb ^ ((k>>2)&7)) << 2));
                e[j][0] = ffma2(av.x, xv0.x, e[j][0]);
                e[j][0] = ffma2(av.y, xv0.y, e[j][0]);
                e[j][1] = ffma2(av.x, xv1.x, e[j][1]);
                e[j][1] = ffma2(av.y, xv1.y, e[j][1]);
                e[j][2] = ffma2(av.x, xv2.x, e[j][2]);
                e[j][2] = ffma2(av.y, xv2.y, e[j][2]);
                e[j][3] = ffma2(av.x, xv3.x, e[j][3]);
                e[j][3] = ffma2(av.y, xv3.y, e[j][3]);
                if (cg == 0) sa[j] = fadd2(sa[j], fadd2(av.x, av.y));
            }
        }

        float* E = out + b * (K_ * C_);
        #pragma unroll
        for (int j = 0; j < 8; ++j) {
            #pragma unroll
            for (int cj = 0; cj < 4; ++cj) {
                float2 f = unpack2(e[j][cj]);
                atomicAdd(&E[(k0b + j) * C_ + c0 + cj], f.x + f.y);
            }
        }
        if (cg == 0) {
            #pragma unroll
            for (int j = 0; j < 8; ++j) {
                float2 f = unpack2(sa[j]);
                atomicAdd(&g_asum[b*K_ + k0b + j], f.x + f.y);
            }
        }
    }
}

// ---------------------------------------------------------------------------
__global__ void enc_final(const float* __restrict__ cwg, float* __restrict__ out) {
    int i = blockIdx.x * 256 + threadIdx.x;
    if (i >= E_ELEMS) return;
    int c  = i & 63;
    int bk = i >> 6;
    int k  = bk & 31;
    out[i] -= g_asum[bk] * cwg[k*64 + c];
}

// ---------------------------------------------------------------------------
extern "C" void kernel_launch(void* const* d_in, const int* in_sizes, int n_in,
                              void* d_out, int out_size) {
    const float* X   = (const float*)d_in[0];
    const float* cwg = (const float*)d_in[1];
    const float* scl = (const float*)d_in[2];
    float* out = (float*)d_out;

    const int smem_bytes = (64*XS + 32*LS + 64*CWS + 256 + 64) * 4; // 110,336 B
    cudaFuncSetAttribute(enc_main, cudaFuncAttributeMaxDynamicSharedMemorySize,
                         smem_bytes);

    enc_init<<<32, 256>>>(out);
    enc_main<<<2048, 256, smem_bytes>>>(X, cwg, scl, out);
    enc_final<<<32, 256>>>(cwg, out);
}

// round 8
// speedup vs baseline: 1.8291x; 1.8291x over previous
#include <cuda_runtime.h>

#define B_  4
#define C_  64
#define K_  32
#define N_  131072           // D*H*W
#define XS  260              // X tile row stride (words)
#define LS  260              // L/A tile row stride (words)
#define CWS 36               // transposed codeword stride
#define E_ELEMS (B_*K_*C_)   // 8192

__device__ float g_asum[B_*K_];

typedef unsigned long long u64;

__device__ __forceinline__ u64 ffma2(u64 a, u64 b, u64 c) {
    u64 d; asm("fma.rn.f32x2 %0, %1, %2, %3;" : "=l"(d) : "l"(a), "l"(b), "l"(c));
    return d;
}
__device__ __forceinline__ u64 fadd2(u64 a, u64 b) {
    u64 d; asm("add.rn.f32x2 %0, %1, %2;" : "=l"(d) : "l"(a), "l"(b));
    return d;
}
__device__ __forceinline__ u64 pack2(float lo, float hi) {
    u64 d; asm("mov.b64 %0, {%1, %2};" : "=l"(d) : "f"(lo), "f"(hi));
    return d;
}
__device__ __forceinline__ float2 unpack2(u64 v) {
    float2 r; asm("mov.b64 {%0, %1}, %2;" : "=f"(r.x), "=f"(r.y) : "l"(v));
    return r;
}

// ---------------------------------------------------------------------------
__global__ void enc_init(float* __restrict__ out) {
    int i = blockIdx.x * 256 + threadIdx.x;
    if (i < E_ELEMS) out[i] = 0.0f;
    if (i < B_*K_)   g_asum[i] = 0.0f;
}

// ---------------------------------------------------------------------------
__global__ __launch_bounds__(256, 2) void enc_main(
    const float* __restrict__ X,    // (B, C, N)
    const float* __restrict__ cwg,  // (K, C)
    const float* __restrict__ sclg, // (K,)
    float* __restrict__ out)        // [E | coefA]
{
    extern __shared__ float sm[];
    float* Xs  = sm;                  // 64*260  X tile, swizzled
    float* Lb  = Xs + 64*XS;          // 32*260  logits -> A, swizzled
    float* cwt = Lb + 32*LS;          // 64*36   codewords^T pre-scaled by -2*scl
    float* x2s = cwt + 64*CWS;        // 256
    float* cc  = x2s + 256;           // 64  (float2 per k: scl, scl*|c|^2)

    const int tid = threadIdx.x;
    const int b   = blockIdx.x >> 9;
    const int n0  = (blockIdx.x & 511) << 8;

    // ---- stage X tile, swizzled: word(c,n) = c*XS + ((n4 ^ ((c>>2)&7))<<2 | n&3)
    const float* Xb = X + (size_t)b * C_ * N_ + n0;
    #pragma unroll
    for (int i = 0; i < 16; ++i) {
        int f = i * 256 + tid;
        int c = f >> 6, q = f & 63;          // q = n4
        float4 v = *(const float4*)(Xb + (size_t)c * N_ + q * 4);
        int sc = (c >> 2) & 7;
        *(float4*)(Xs + c * XS + ((q ^ sc) << 2)) = v;
    }
    // ---- stage codewords transposed + pre-scaled by -2*scl[k]
    #pragma unroll
    for (int i = 0; i < 8; ++i) {
        int f = i * 256 + tid;               // f = k*64 + c
        int k = f >> 6, c = f & 63;
        cwt[c * CWS + k] = -2.0f * __ldg(&sclg[k]) * cwg[f];
    }
    // ---- per-k softmax constants straight from global (tiny, L2-hot)
    if (tid < K_) {
        float s = 0.f;
        #pragma unroll
        for (int c = 0; c < C_; ++c) { float w = cwg[tid*C_ + c]; s = fmaf(w, w, s); }
        float sc = sclg[tid];
        *(float2*)(cc + tid * 2) = make_float2(sc, sc * s);
    }
    __syncthreads();

    // ---- Phase 1: scaled-dot GEMM, 4k x 8n per thread, n-paired f32x2 ----
    const int k0  = (tid & 7) * 4;
    const int nt  = (tid >> 3) * 8;
    const int n4a = nt >> 2;                 // even
    u64 acc[4][4];                           // [npair][k] ; holds -2*scl*dot
    u64 x2a[4];
    #pragma unroll
    for (int i = 0; i < 4; ++i) {
        x2a[i] = 0ull;
        #pragma unroll
        for (int j = 0; j < 4; ++j) acc[i][j] = 0ull;
    }

    #pragma unroll 8
    for (int c = 0; c < 64; ++c) {
        int sc = (c >> 2) & 7;
        const float* xr = Xs + c * XS;
        ulonglong2 xa = *(const ulonglong2*)(xr + (( n4a      ^ sc) << 2));
        ulonglong2 xb = *(const ulonglong2*)(xr + (((n4a + 1) ^ sc) << 2));
        float4 w = *(const float4*)(cwt + c * CWS + k0);
        u64 w0 = pack2(w.x, w.x), w1 = pack2(w.y, w.y);
        u64 w2 = pack2(w.z, w.z), w3 = pack2(w.w, w.w);
        acc[0][0] = ffma2(xa.x, w0, acc[0][0]);
        acc[0][1] = ffma2(xa.x, w1, acc[0][1]);
        acc[0][2] = ffma2(xa.x, w2, acc[0][2]);
        acc[0][3] = ffma2(xa.x, w3, acc[0][3]);
        acc[1][0] = ffma2(xa.y, w0, acc[1][0]);
        acc[1][1] = ffma2(xa.y, w1, acc[1][1]);
        acc[1][2] = ffma2(xa.y, w2, acc[1][2]);
        acc[1][3] = ffma2(xa.y, w3, acc[1][3]);
        acc[2][0] = ffma2(xb.x, w0, acc[2][0]);
        acc[2][1] = ffma2(xb.x, w1, acc[2][1]);
        acc[2][2] = ffma2(xb.x, w2, acc[2][2]);
        acc[2][3] = ffma2(xb.x, w3, acc[2][3]);
        acc[3][0] = ffma2(xb.y, w0, acc[3][0]);
        acc[3][1] = ffma2(xb.y, w1, acc[3][1]);
        acc[3][2] = ffma2(xb.y, w2, acc[3][2]);
        acc[3][3] = ffma2(xb.y, w3, acc[3][3]);
        x2a[0] = ffma2(xa.x, xa.x, x2a[0]);
        x2a[1] = ffma2(xa.y, xa.y, x2a[1]);
        x2a[2] = ffma2(xb.x, xb.x, x2a[2]);
        x2a[3] = ffma2(xb.y, xb.y, x2a[3]);
    }
    // store to Lb (swizzled): row k0+j, word nt+2i
    {
        const int sk = tid & 7;              // (k0+j)>>2 for j<4
        #pragma unroll
        for (int j = 0; j < 4; ++j) {
            float* row = Lb + (k0 + j) * LS;
            #pragma unroll
            for (int i = 0; i < 4; ++i) {
                int w4 = (n4a + (i >> 1)) ^ sk;
                *(u64*)(row + (w4 << 2) + 2 * (i & 1)) = acc[i][j];
            }
        }
        if ((tid & 7) == 0) {
            #pragma unroll
            for (int i = 0; i < 4; ++i) *(u64*)(x2s + nt + 2*i) = x2a[i];
        }
    }
    __syncthreads();

    // ---- Softmax per n = tid; coefA out; A back into Lb (same words) ----
    {
        float x2 = x2s[tid];
        const int n4t = tid >> 2, nlo = tid & 3;
        float lg[K_];
        float mx = -1e30f;
        #pragma unroll
        for (int k = 0; k < K_; ++k) {
            float2 t = *(const float2*)(cc + 2 * k);
            float d = Lb[k * LS + (((n4t) ^ ((k >> 2) & 7)) << 2) + nlo];
            float l = d + fmaf(t.x, x2, t.y);     // -2*scl*dot + scl*x2 + scl*c2
            lg[k] = l;
            mx = fmaxf(mx, l);
        }
        float s = 0.f;
        #pragma unroll
        for (int k = 0; k < K_; ++k) { float e = __expf(lg[k] - mx); lg[k] = e; s += e; }
        float inv = __fdividef(1.f, s);
        float* coefA = out + E_ELEMS + (size_t)b * K_ * N_ + n0 + tid;
        #pragma unroll
        for (int k = 0; k < K_; ++k) {
            float a = lg[k] * inv;
            coefA[(size_t)k * N_] = a;
            Lb[k * LS + (((n4t) ^ ((k >> 2) & 7)) << 2) + nlo] = a;
        }
    }
    __syncthreads();

    // ---- Phase 2: A^T X, 4k x 4c per thread over 128 n (n-split 2) ----
    {
        const int ns  = tid >> 7;            // 0..1 (128 n each)
        const int pos = tid & 127;
        const int kg  = pos >> 4;            // 0..7 -> k rows 4kg..4kg+3
        const int cg  = pos & 15;            // 0..15 -> c cols 4cg..4cg+3
        const int k0b = kg * 4, c0 = cg * 4;
        const int nb0 = ns * 32;             // n4 base
        const int scx = cg & 7;              // X swizzle key for c = 4cg+cj
        // A swizzle key: k = 4kg+j (j<4) -> (k>>2)&7 = kg, uniform over j

        u64 e[4][4];                         // [k][c]
        u64 sa[4];
        #pragma unroll
        for (int j = 0; j < 4; ++j) {
            sa[j] = 0ull;
            #pragma unroll
            for (int cj = 0; cj < 4; ++cj) e[j][cj] = 0ull;
        }

        const float* Ar = Lb + k0b * LS;

        #pragma unroll 2
        for (int n4 = 0; n4 < 32; ++n4) {
            const int nb = nb0 + n4;
            const int wx = (nb ^ scx) << 2;
            const int wa = (nb ^ kg) << 2;
            ulonglong2 xv0 = *(const ulonglong2*)(Xs + (c0+0)*XS + wx);
            ulonglong2 xv1 = *(const ulonglong2*)(Xs + (c0+1)*XS + wx);
            ulonglong2 xv2 = *(const ulonglong2*)(Xs + (c0+2)*XS + wx);
            ulonglong2 xv3 = *(const ulonglong2*)(Xs + (c0+3)*XS + wx);
            ulonglong2 a0  = *(const ulonglong2*)(Ar + 0*LS + wa);
            ulonglong2 a1  = *(const ulonglong2*)(Ar + 1*LS + wa);
            ulonglong2 a2  = *(const ulonglong2*)(Ar + 2*LS + wa);
            ulonglong2 a3  = *(const ulonglong2*)(Ar + 3*LS + wa);

            e[0][0] = ffma2(a0.x, xv0.x, e[0][0]); e[0][0] = ffma2(a0.y, xv0.y, e[0][0]);
            e[0][1] = ffma2(a0.x, xv1.x, e[0][1]); e[0][1] = ffma2(a0.y, xv1.y, e[0][1]);
            e[0][2] = ffma2(a0.x, xv2.x, e[0][2]); e[0][2] = ffma2(a0.y, xv2.y, e[0][2]);
            e[0][3] = ffma2(a0.x, xv3.x, e[0][3]); e[0][3] = ffma2(a0.y, xv3.y, e[0][3]);
            e[1][0] = ffma2(a1.x, xv0.x, e[1][0]); e[1][0] = ffma2(a1.y, xv0.y, e[1][0]);
            e[1][1] = ffma2(a1.x, xv1.x, e[1][1]); e[1][1] = ffma2(a1.y, xv1.y, e[1][1]);
            e[1][2] = ffma2(a1.x, xv2.x, e[1][2]); e[1][2] = ffma2(a1.y, xv2.y, e[1][2]);
            e[1][3] = ffma2(a1.x, xv3.x, e[1][3]); e[1][3] = ffma2(a1.y, xv3.y, e[1][3]);
            e[2][0] = ffma2(a2.x, xv0.x, e[2][0]); e[2][0] = ffma2(a2.y, xv0.y, e[2][0]);
            e[2][1] = ffma2(a2.x, xv1.x, e[2][1]); e[2][1] = ffma2(a2.y, xv1.y, e[2][1]);
            e[2][2] = ffma2(a2.x, xv2.x, e[2][2]); e[2][2] = ffma2(a2.y, xv2.y, e[2][2]);
            e[2][3] = ffma2(a2.x, xv3.x, e[2][3]); e[2][3] = ffma2(a2.y, xv3.y, e[2][3]);
            e[3][0] = ffma2(a3.x, xv0.x, e[3][0]); e[3][0] = ffma2(a3.y, xv0.y, e[3][0]);
            e[3][1] = ffma2(a3.x, xv1.x, e[3][1]); e[3][1] = ffma2(a3.y, xv1.y, e[3][1]);
            e[3][2] = ffma2(a3.x, xv2.x, e[3][2]); e[3][2] = ffma2(a3.y, xv2.y, e[3][2]);
            e[3][3] = ffma2(a3.x, xv3.x, e[3][3]); e[3][3] = ffma2(a3.y, xv3.y, e[3][3]);
            if (cg == 0) {
                sa[0] = fadd2(sa[0], fadd2(a0.x, a0.y));
                sa[1] = fadd2(sa[1], fadd2(a1.x, a1.y));
                sa[2] = fadd2(sa[2], fadd2(a2.x, a2.y));
                sa[3] = fadd2(sa[3], fadd2(a3.x, a3.y));
            }
        }

        float* E = out + b * (K_ * C_);
        #pragma unroll
        for (int j = 0; j < 4; ++j) {
            #pragma unroll
            for (int cj = 0; cj < 4; ++cj) {
                float2 f = unpack2(e[j][cj]);
                atomicAdd(&E[(k0b + j) * C_ + c0 + cj], f.x + f.y);
            }
        }
        if (cg == 0) {
            #pragma unroll
            for (int j = 0; j < 4; ++j) {
                float2 f = unpack2(sa[j]);
                atomicAdd(&g_asum[b*K_ + k0b + j], f.x + f.y);
            }
        }
    }
}

// ---------------------------------------------------------------------------
__global__ void enc_final(const float* __restrict__ cwg, float* __restrict__ out) {
    int i = blockIdx.x * 256 + threadIdx.x;
    if (i >= E_ELEMS) return;
    int c  = i & 63;
    int bk = i >> 6;
    int k  = bk & 31;
    out[i] -= g_asum[bk] * cwg[k*64 + c];
}

// ---------------------------------------------------------------------------
extern "C" void kernel_launch(void* const* d_in, const int* in_sizes, int n_in,
                              void* d_out, int out_size) {
    const float* X   = (const float*)d_in[0];
    const float* cwg = (const float*)d_in[1];
    const float* scl = (const float*)d_in[2];
    float* out = (float*)d_out;

    const int smem_bytes = (64*XS + 32*LS + 64*CWS + 256 + 64) * 4; // 110,336 B
    cudaFuncSetAttribute(enc_main, cudaFuncAttributeMaxDynamicSharedMemorySize,
                         smem_bytes);

    enc_init<<<32, 256>>>(out);
    enc_main<<<2048, 256, smem_bytes>>>(X, cwg, scl, out);
    enc_final<<<32, 256>>>(cwg, out);
}

// round 9
// speedup vs baseline: 2.4784x; 1.3550x over previous
#include <cuda_runtime.h>

#define B_  4
#define C_  64
#define K_  32
#define N_  131072           // D*H*W
#define XS  260              // X tile row stride (words)
#define LS  260              // L/A tile row stride (words)
#define CWS 36               // transposed codeword stride
#define E_ELEMS (B_*K_*C_)   // 8192

__device__ float g_asum[B_*K_];

typedef unsigned long long u64;

__device__ __forceinline__ u64 ffma2(u64 a, u64 b, u64 c) {
    u64 d; asm("fma.rn.f32x2 %0, %1, %2, %3;" : "=l"(d) : "l"(a), "l"(b), "l"(c));
    return d;
}
__device__ __forceinline__ u64 fadd2(u64 a, u64 b) {
    u64 d; asm("add.rn.f32x2 %0, %1, %2;" : "=l"(d) : "l"(a), "l"(b));
    return d;
}
__device__ __forceinline__ u64 pack2(float lo, float hi) {
    u64 d; asm("mov.b64 %0, {%1, %2};" : "=l"(d) : "f"(lo), "f"(hi));
    return d;
}
__device__ __forceinline__ float2 unpack2(u64 v) {
    float2 r; asm("mov.b64 {%0, %1}, %2;" : "=f"(r.x), "=f"(r.y) : "l"(v));
    return r;
}

// ---------------------------------------------------------------------------
__global__ void enc_init(float* __restrict__ out) {
    int i = blockIdx.x * 256 + threadIdx.x;
    if (i < E_ELEMS) out[i] = 0.0f;
    if (i < B_*K_)   g_asum[i] = 0.0f;
}

// ---------------------------------------------------------------------------
__global__ __launch_bounds__(256, 2) void enc_main(
    const float* __restrict__ X,    // (B, C, N)
    const float* __restrict__ cwg,  // (K, C)
    const float* __restrict__ sclg, // (K,)
    float* __restrict__ out)        // [E | coefA]
{
    extern __shared__ float sm[];
    float* Xs  = sm;                  // 64*260  X tile, [c][n] linear
    float* Lb  = Xs + 64*XS;          // 32*260  logits -> A, [k][n] linear
    float* cwt = Lb + 32*LS;          // 64*36   codewords^T
    float* x2s = cwt + 64*CWS;        // 256
    float* scl = x2s + 256;           // 32
    float* c4  = scl + 32;            // 32*4  (scl, -2*scl, scl*c2, 0)

    const int tid = threadIdx.x;
    const int b   = blockIdx.x >> 9;
    const int n0  = (blockIdx.x & 511) << 8;

    // ---- stage X tile (vectorized, coalesced, linear layout) ----
    const float* Xb = X + (size_t)b * C_ * N_ + n0;
    #pragma unroll
    for (int i = 0; i < 16; ++i) {
        int f = i * 256 + tid;
        int c = f >> 6, q = f & 63;
        float4 v = *(const float4*)(Xb + (size_t)c * N_ + q * 4);
        *(float4*)(Xs + c * XS + q * 4) = v;
    }
    // ---- stage codewords transposed [c][k] ----
    #pragma unroll
    for (int i = 0; i < 8; ++i) {
        int f = i * 256 + tid;        // f = k*64 + c
        cwt[(f & 63) * CWS + (f >> 6)] = cwg[f];
    }
    if (tid < K_) scl[tid] = sclg[tid];
    __syncthreads();

    if (tid < K_) {
        float s = 0.f;
        #pragma unroll
        for (int c = 0; c < C_; ++c) { float w = cwt[c*CWS + tid]; s = fmaf(w, w, s); }
        float sc = scl[tid];
        float4 v; v.x = sc; v.y = -2.f * sc; v.z = sc * s; v.w = 0.f;
        *(float4*)(c4 + tid * 4) = v;
    }

    // ---- Phase 1: logits GEMM (dots only), 8n x 4k per thread, n-paired ----
    const int k0 = (tid & 7) * 4;
    const int nt = (tid >> 3) * 8;
    u64 acc[4][4];                    // [npair][k]
    u64 x2a[4];
    #pragma unroll
    for (int i = 0; i < 4; ++i) {
        x2a[i] = 0ull;
        #pragma unroll
        for (int j = 0; j < 4; ++j) acc[i][j] = 0ull;
    }

    #pragma unroll 8
    for (int c = 0; c < 64; ++c) {
        ulonglong2 xa = *(const ulonglong2*)(Xs + c * XS + nt);
        ulonglong2 xb = *(const ulonglong2*)(Xs + c * XS + nt + 4);
        float4 w = *(const float4*)(cwt + c * CWS + k0);
        u64 w0 = pack2(w.x, w.x), w1 = pack2(w.y, w.y);
        u64 w2 = pack2(w.z, w.z), w3 = pack2(w.w, w.w);
        acc[0][0] = ffma2(xa.x, w0, acc[0][0]);
        acc[0][1] = ffma2(xa.x, w1, acc[0][1]);
        acc[0][2] = ffma2(xa.x, w2, acc[0][2]);
        acc[0][3] = ffma2(xa.x, w3, acc[0][3]);
        acc[1][0] = ffma2(xa.y, w0, acc[1][0]);
        acc[1][1] = ffma2(xa.y, w1, acc[1][1]);
        acc[1][2] = ffma2(xa.y, w2, acc[1][2]);
        acc[1][3] = ffma2(xa.y, w3, acc[1][3]);
        acc[2][0] = ffma2(xb.x, w0, acc[2][0]);
        acc[2][1] = ffma2(xb.x, w1, acc[2][1]);
        acc[2][2] = ffma2(xb.x, w2, acc[2][2]);
        acc[2][3] = ffma2(xb.x, w3, acc[2][3]);
        acc[3][0] = ffma2(xb.y, w0, acc[3][0]);
        acc[3][1] = ffma2(xb.y, w1, acc[3][1]);
        acc[3][2] = ffma2(xb.y, w2, acc[3][2]);
        acc[3][3] = ffma2(xb.y, w3, acc[3][3]);
        x2a[0] = ffma2(xa.x, xa.x, x2a[0]);
        x2a[1] = ffma2(xa.y, xa.y, x2a[1]);
        x2a[2] = ffma2(xb.x, xb.x, x2a[2]);
        x2a[3] = ffma2(xb.y, xb.y, x2a[3]);
    }
    #pragma unroll
    for (int j = 0; j < 4; ++j)
        #pragma unroll
        for (int i = 0; i < 4; ++i)
            *(u64*)(Lb + (k0 + j) * LS + nt + 2*i) = acc[i][j];
    if ((tid & 7) == 0) {
        #pragma unroll
        for (int i = 0; i < 4; ++i) *(u64*)(x2s + nt + 2*i) = x2a[i];
    }
    __syncthreads();

    // ---- Softmax per n = tid, write coefA + A (in place over Lb) ----
    {
        float x2 = x2s[tid];
        float lg[K_];
        float mx = -1e30f;
        #pragma unroll
        for (int k = 0; k < K_; ++k) {
            float4 cc = *(const float4*)(c4 + k * 4);
            float d = Lb[k * LS + tid];
            float l = fmaf(cc.y, d, fmaf(cc.x, x2, cc.z));
            lg[k] = l;
            mx = fmaxf(mx, l);
        }
        float s = 0.f;
        #pragma unroll
        for (int k = 0; k < K_; ++k) { float e = __expf(lg[k] - mx); lg[k] = e; s += e; }
        float inv = __fdividef(1.f, s);
        float* coefA = out + E_ELEMS + (size_t)b * K_ * N_ + n0 + tid;
        #pragma unroll
        for (int k = 0; k < K_; ++k) {
            float a = lg[k] * inv;
            coefA[(size_t)k * N_] = a;     // coalesced per k
            Lb[k * LS + tid] = a;          // same words this thread read -> safe
        }
    }
    __syncthreads();

    // ---- Phase 2: A^T X, 4k x 4c per thread, c interleaved (c = cg + 16*cj),
    //      n-split 2, LINEAR addressing (conflict-free: bank = 4*cg mod 32) ----
    {
        const int ns  = tid >> 7;            // 0..1 (128 n each)
        const int pos = tid & 127;
        const int kg  = pos >> 4;            // 0..7 -> k rows 4kg..4kg+3
        const int cg  = pos & 15;            // c cols: cg, cg+16, cg+32, cg+48
        const int k0b = kg * 4;
        const int nb  = ns * 128;

        const float* Ar = Lb + k0b * LS + nb;
        const float* Xc = Xs + cg  * XS + nb;

        u64 e[4][4];                         // [k][cj]
        u64 sa[4];
        #pragma unroll
        for (int j = 0; j < 4; ++j) {
            sa[j] = 0ull;
            #pragma unroll
            for (int cj = 0; cj < 4; ++cj) e[j][cj] = 0ull;
        }

        #pragma unroll 2
        for (int n = 0; n < 128; n += 4) {
            ulonglong2 x0 = *(const ulonglong2*)(Xc +  0 * XS + n);
            ulonglong2 x1 = *(const ulonglong2*)(Xc + 16 * XS + n);
            ulonglong2 x2v = *(const ulonglong2*)(Xc + 32 * XS + n);
            ulonglong2 x3 = *(const ulonglong2*)(Xc + 48 * XS + n);
            ulonglong2 a0 = *(const ulonglong2*)(Ar + 0 * LS + n);
            ulonglong2 a1 = *(const ulonglong2*)(Ar + 1 * LS + n);
            ulonglong2 a2 = *(const ulonglong2*)(Ar + 2 * LS + n);
            ulonglong2 a3 = *(const ulonglong2*)(Ar + 3 * LS + n);

            e[0][0] = ffma2(a0.x, x0.x,  e[0][0]); e[0][0] = ffma2(a0.y, x0.y,  e[0][0]);
            e[0][1] = ffma2(a0.x, x1.x,  e[0][1]); e[0][1] = ffma2(a0.y, x1.y,  e[0][1]);
            e[0][2] = ffma2(a0.x, x2v.x, e[0][2]); e[0][2] = ffma2(a0.y, x2v.y, e[0][2]);
            e[0][3] = ffma2(a0.x, x3.x,  e[0][3]); e[0][3] = ffma2(a0.y, x3.y,  e[0][3]);
            e[1][0] = ffma2(a1.x, x0.x,  e[1][0]); e[1][0] = ffma2(a1.y, x0.y,  e[1][0]);
            e[1][1] = ffma2(a1.x, x1.x,  e[1][1]); e[1][1] = ffma2(a1.y, x1.y,  e[1][1]);
            e[1][2] = ffma2(a1.x, x2v.x, e[1][2]); e[1][2] = ffma2(a1.y, x2v.y, e[1][2]);
            e[1][3] = ffma2(a1.x, x3.x,  e[1][3]); e[1][3] = ffma2(a1.y, x3.y,  e[1][3]);
            e[2][0] = ffma2(a2.x, x0.x,  e[2][0]); e[2][0] = ffma2(a2.y, x0.y,  e[2][0]);
            e[2][1] = ffma2(a2.x, x1.x,  e[2][1]); e[2][1] = ffma2(a2.y, x1.y,  e[2][1]);
            e[2][2] = ffma2(a2.x, x2v.x, e[2][2]); e[2][2] = ffma2(a2.y, x2v.y, e[2][2]);
            e[2][3] = ffma2(a2.x, x3.x,  e[2][3]); e[2][3] = ffma2(a2.y, x3.y,  e[2][3]);
            e[3][0] = ffma2(a3.x, x0.x,  e[3][0]); e[3][0] = ffma2(a3.y, x0.y,  e[3][0]);
            e[3][1] = ffma2(a3.x, x1.x,  e[3][1]); e[3][1] = ffma2(a3.y, x1.y,  e[3][1]);
            e[3][2] = ffma2(a3.x, x2v.x, e[3][2]); e[3][2] = ffma2(a3.y, x2v.y, e[3][2]);
            e[3][3] = ffma2(a3.x, x3.x,  e[3][3]); e[3][3] = ffma2(a3.y, x3.y,  e[3][3]);
            sa[0] = fadd2(sa[0], fadd2(a0.x, a0.y));
            sa[1] = fadd2(sa[1], fadd2(a1.x, a1.y));
            sa[2] = fadd2(sa[2], fadd2(a2.x, a2.y));
            sa[3] = fadd2(sa[3], fadd2(a3.x, a3.y));
        }

        float* E = out + b * (K_ * C_);
        #pragma unroll
        for (int j = 0; j < 4; ++j) {
            #pragma unroll
            for (int cj = 0; cj < 4; ++cj) {
                float2 f = unpack2(e[j][cj]);
                atomicAdd(&E[(k0b + j) * C_ + cg + 16 * cj], f.x + f.y);
            }
        }
        if (cg == 0) {
            #pragma unroll
            for (int j = 0; j < 4; ++j) {
                float2 f = unpack2(sa[j]);
                atomicAdd(&g_asum[b*K_ + k0b + j], f.x + f.y);
            }
        }
    }
}

// ---------------------------------------------------------------------------
__global__ void enc_final(const float* __restrict__ cwg, float* __restrict__ out) {
    int i = blockIdx.x * 256 + threadIdx.x;
    if (i >= E_ELEMS) return;
    int c  = i & 63;
    int bk = i >> 6;
    int k  = bk & 31;
    out[i] -= g_asum[bk] * cwg[k*64 + c];
}

// ---------------------------------------------------------------------------
extern "C" void kernel_launch(void* const* d_in, const int* in_sizes, int n_in,
                              void* d_out, int out_size) {
    const float* X   = (const float*)d_in[0];
    const float* cwg = (const float*)d_in[1];
    const float* scl = (const float*)d_in[2];
    float* out = (float*)d_out;

    const int smem_bytes = (64*XS + 32*LS + 64*CWS + 256 + 32 + 128) * 4; // 110,592 B
    cudaFuncSetAttribute(enc_main, cudaFuncAttributeMaxDynamicSharedMemorySize,
                         smem_bytes);

    enc_init<<<32, 256>>>(out);
    enc_main<<<2048, 256, smem_bytes>>>(X, cwg, scl, out);
    enc_final<<<32, 256>>>(cwg, out);
}